// round 12
// baseline (speedup 1.0000x reference)
#include <cuda_runtime.h>
#include <cstdint>
#include <math.h>

#define GO_TAG 1
#define NEGV   -10000.0f
#define K_     64
#define MAXELEMS_ (1024u * 512u * 64u)
#define ORDER_MAX 65536
#define NWORK_BLOCKS 592   // 4 per SM on 148-SM GB300

// Scratch: alpha history rows 1..len-1 per batch, trans tables, scheduler.
__device__ float g_trans[K_ * K_];    // trans[i][j] = score(i -> j)
__device__ float g_transT[K_ * K_];   // transT[j][i] = trans[i][j]
__device__ float g_alpha[MAXELEMS_];
__device__ int   g_ctr;
__device__ int   g_order[ORDER_MAX];

__device__ __forceinline__ void cp_async16(uint32_t saddr, const void* gptr) {
    asm volatile("cp.async.ca.shared.global [%0], [%1], 16;"
                 :: "r"(saddr), "l"(gptr));
}
__device__ __forceinline__ void cp_commit() {
    asm volatile("cp.async.commit_group;");
}
template <int N>
__device__ __forceinline__ void cp_wait() {
    asm volatile("cp.async.wait_group %0;" :: "n"(N));
}

// ---------------------------------------------------------------------------
// Kernel 1: trans = log_softmax(A + mask * NEG, axis=-1) + transpose.
// ---------------------------------------------------------------------------
__global__ void __launch_bounds__(64)
trans_kernel(const float* __restrict__ c0, const float* __restrict__ c1) {
    __shared__ float  s_m[2];
    __shared__ double s_s[2];
    const int r = blockIdx.x;
    const int c = threadIdx.x;
    const int w = c >> 5;
    const int lane = c & 31;

    unsigned u0 = ((const unsigned*)c0)[r * K_ + c];
    const bool c0_is_mask = __syncthreads_and(u0 <= 1u);
    const int*   mask = (const int*)(c0_is_mask ? c0 : c1);
    const float* A    = c0_is_mask ? c1 : c0;

    float x = A[r * K_ + c] + (mask[r * K_ + c] ? NEGV : 0.0f);

    float m = x;
    #pragma unroll
    for (int d = 16; d > 0; d >>= 1) m = fmaxf(m, __shfl_xor_sync(~0u, m, d));
    if (lane == 0) s_m[w] = m;
    __syncthreads();
    m = fmaxf(s_m[0], s_m[1]);

    double e = exp((double)(x - m));
    #pragma unroll
    for (int d = 16; d > 0; d >>= 1) e += __shfl_xor_sync(~0u, e, d);
    if (lane == 0) s_s[w] = e;
    __syncthreads();
    const float l = (float)log(s_s[0] + s_s[1]);

    const float v = (x - m) - l;
    g_trans[r * K_ + c]  = v;
    g_transT[c * K_ + r] = v;
}

// ---------------------------------------------------------------------------
// Kernel 1b: counting-sort sequence indices by DESCENDING length (LPT order)
// into g_order; also resets the work counter. 1 block, 1024 threads.
// ---------------------------------------------------------------------------
__global__ void __launch_bounds__(1024)
sort_kernel(const int* __restrict__ lengths, int T, int B) {
    __shared__ int h[1024];
    __shared__ int h2[1024];
    __shared__ int cur[1024];
    const int tid = threadIdx.x;
    if (tid == 0) g_ctr = 0;
    h[tid] = 0;
    __syncthreads();

    for (int i = tid; i < B; i += 1024) {
        int len = lengths[i]; len = len < 1 ? 1 : (len > T ? T : len);
        int key = T - len; key = key < 0 ? 0 : (key > 1023 ? 1023 : key);
        atomicAdd(&h[key], 1);
    }
    __syncthreads();

    const int cnt = h[tid];
    int* src = h;
    int* dst = h2;
    for (int d = 1; d < 1024; d <<= 1) {
        int v = src[tid];
        if (tid >= d) v += src[tid - d];
        dst[tid] = v;
        __syncthreads();
        int* tmp = src; src = dst; dst = tmp;
    }
    cur[tid] = src[tid] - cnt;   // exclusive prefix = scatter base
    __syncthreads();

    for (int i = tid; i < B; i += 1024) {
        int len = lengths[i]; len = len < 1 ? 1 : (len > T ? T : len);
        int key = T - len; key = key < 0 ? 0 : (key > 1023 ? 1023 : key);
        int pos = atomicAdd(&cur[key], 1);
        if (pos < ORDER_MAX) g_order[pos] = i;
    }
}

// ---------------------------------------------------------------------------
// Kernel 2: PERSISTENT fused Viterbi. Each 128-thread block = 2 independent
// 64-thread groups; each group repeatedly claims the next sequence (LPT order)
// from a global counter. Per sequence: scalar reg-resident trans column,
// smem alpha ping-pong, cp.async unary staging + path-only backward.
// ---------------------------------------------------------------------------
__global__ void __launch_bounds__(128, 4)
viterbi_kernel(const float* __restrict__ unary,
               const int* __restrict__ lengths,
               float* __restrict__ out,
               int T, int B) {
    __shared__ __align__(16) float s_transT[K_ * K_];
    __shared__ __align__(16) float s_alpha[2][2][K_];   // [g][buf][j]
    __shared__ __align__(16) float s_u[2][2][8][K_];    // [g][buf][s][j]
    __shared__ int s_last[2];
    __shared__ int s_idx[2];

    const int tid = threadIdx.x;
    const int g = tid >> 6;
    const int j = tid & 63;
    const int nbar = 1 + g;

    #define GBAR() asm volatile("bar.sync %0, 64;" :: "r"(nbar) : "memory")

    const uint32_t su_base =
        (uint32_t)__cvta_generic_to_shared(&s_u[g][0][0][0]);
    const size_t bstride = (size_t)T * K_;

    // One-time: shared transposed table + register transition column.
    {
        const float4* src = (const float4*)g_transT;
        float4* dst = (float4*)s_transT;
        #pragma unroll
        for (int q = 0; q < 8; q++) dst[tid + q * 128] = src[tid + q * 128];
    }
    float tr[K_];
    #pragma unroll
    for (int i = 0; i < K_; i++) tr[i] = g_trans[i * K_ + j];
    __syncthreads();

    // -------------------- persistent work loop --------------------
    for (;;) {
        if (j == 0) s_idx[g] = atomicAdd(&g_ctr, 1);
        GBAR();
        const int idx = s_idx[g];
        if (idx >= B) break;                 // uniform per group
        const int b = g_order[idx];

        int len = lengths[b];
        len = len < 1 ? 1 : (len > T ? T : len);
        const float* ub = unary + (size_t)b * bstride;
        float* arow = g_alpha + (size_t)b * bstride;

        // Prefetch first unary chunk (steps 1..8 -> rows 0..7, clamped).
        {
            #pragma unroll
            for (int rr = 0; rr < 2; rr++) {
                int l = j + rr * 64;
                int s = l >> 4;
                int c = (l & 15) * 4;
                int row = s; if (row > T - 1) row = T - 1;
                cp_async16(su_base + (uint32_t)(s * K_ + c) * 4,
                           ub + (size_t)row * K_ + c);
            }
            cp_commit();
        }

        s_alpha[g][0][j] = (j == GO_TAG) ? 0.0f : NEGV;
        GBAR();

        // ---------------- forward ----------------
        int cbuf = 0;
        for (int t0 = 1; t0 <= len; t0 += 8) {
            if (t0 + 8 <= len) {
                #pragma unroll
                for (int rr = 0; rr < 2; rr++) {
                    int l = j + rr * 64;
                    int s = l >> 4;
                    int c = (l & 15) * 4;
                    int row = t0 + 7 + s;
                    if (row > T - 1) row = T - 1;
                    cp_async16(su_base + (uint32_t)(((cbuf ^ 1) * 8 + s) * K_ + c) * 4,
                               ub + (size_t)row * K_ + c);
                }
            }
            cp_commit();      // always commit (possibly empty)
            cp_wait<1>();     // current chunk complete
            GBAR();

            const int tend = (t0 + 7 < len) ? t0 + 7 : len;
            #pragma unroll
            for (int s = 0; s < 8; s++) {
                const int t = t0 + s;
                if (t <= tend) {             // uniform per group
                    const float u = s_u[g][cbuf][s][j];
                    const float4* av = (const float4*)s_alpha[g][(t - 1) & 1];
                    float4 v = av[0];
                    float m0 = v.x + tr[0];
                    float m1 = v.y + tr[1];
                    float m2 = v.z + tr[2];
                    float m3 = v.w + tr[3];
                    #pragma unroll
                    for (int q = 1; q < 16; q++) {
                        v = av[q];
                        m0 = fmaxf(m0, v.x + tr[4 * q + 0]);
                        m1 = fmaxf(m1, v.y + tr[4 * q + 1]);
                        m2 = fmaxf(m2, v.z + tr[4 * q + 2]);
                        m3 = fmaxf(m3, v.w + tr[4 * q + 3]);
                    }
                    float a = fmaxf(fmaxf(m0, m1), fmaxf(m2, m3)) + u;
                    s_alpha[g][t & 1][j] = a;
                    if (t < len) arow[(size_t)t * K_ + j] = a;  // rows 1..len-1
                    GBAR();
                }
            }
            cbuf ^= 1;
        }

        // last = argmax_j(final alpha), first-index tiebreak (exact scan).
        if (j == 0) {
            const float* af = s_alpha[g][len & 1];
            float bv = af[0];
            int bi = 0;
            #pragma unroll
            for (int i = 1; i < K_; i++) {
                if (af[i] > bv) { bv = af[i]; bi = i; }
            }
            s_last[g] = bi;
        }
        GBAR();
        const int last = s_last[g];

        // Output positions tau >= len-1 all equal `last`.
        float* ob = out + (size_t)b * T;
        const float lastf = (float)last;
        for (int tau = (len - 1) + j; tau < T; tau += K_) ob[tau] = lastf;

        // ---------------- backward (warp 0 of group) ----------------
        if (j < 32 && len >= 2) {
            const int lane = j;
            int tag = last;

            #pragma unroll
            for (int rr = 0; rr < 4; rr++) {
                int l = lane + rr * 32;
                int s = l >> 4;
                int c = (l & 15) * 4;
                int row = len - 1 - s; if (row < 0) row = 0;
                cp_async16(su_base + (uint32_t)(s * K_ + c) * 4,
                           arow + (size_t)row * K_ + c);
            }
            cp_commit();

            int bbuf = 0;
            for (int tb = len; tb >= 2; tb -= 8) {
                if (tb - 8 >= 2) {
                    #pragma unroll
                    for (int rr = 0; rr < 4; rr++) {
                        int l = lane + rr * 32;
                        int s = l >> 4;
                        int c = (l & 15) * 4;
                        int row = tb - 9 - s; if (row < 0) row = 0;
                        cp_async16(su_base + (uint32_t)(((bbuf ^ 1) * 8 + s) * K_ + c) * 4,
                                   arow + (size_t)row * K_ + c);
                    }
                }
                cp_commit();
                cp_wait<1>();
                __syncwarp();

                const int tlo = (tb - 7 > 2) ? tb - 7 : 2;
                #pragma unroll
                for (int s = 0; s < 8; s++) {
                    const int t = tb - s;
                    if (t >= tlo) {
                        float2 a = ((const float2*)&s_u[g][bbuf][s][0])[lane];
                        float2 tt = ((const float2*)(s_transT + tag * K_))[lane];
                        float c0 = a.x + tt.x;
                        float c1 = a.y + tt.y;
                        float v; int li;
                        if (c0 >= c1) { v = c0; li = 2 * lane; }
                        else          { v = c1; li = 2 * lane + 1; }
                        unsigned bits = __float_as_uint(v);
                        unsigned key = ((int)bits < 0) ? ~bits
                                                       : (bits | 0x80000000u);
                        unsigned mx = __reduce_max_sync(0xffffffffu, key);
                        unsigned sel = (key == mx) ? (unsigned)(K_ - 1 - li) : 0u;
                        unsigned w = __reduce_max_sync(0xffffffffu, sel);
                        tag = (K_ - 1) - (int)w;
                        if (lane == 0) ob[t - 2] = (float)tag;
                    }
                }
                bbuf ^= 1;
            }
        }
        // Protect s_u[g] reuse across sequences.
        GBAR();
    }
    #undef GBAR
}

extern "C" void kernel_launch(void* const* d_in, const int* in_sizes, int n_in,
                              void* d_out, int out_size) {
    // ----- identify inputs by SIZE, not position -----
    int iu = 0;
    for (int i = 1; i < n_in; i++)
        if (in_sizes[i] > in_sizes[iu]) iu = i;

    int pair[2] = {-1, -1};
    int ilen = -1;
    for (int i = 0; i < n_in; i++) {
        if (i == iu) continue;
        for (int k = 0; k < n_in; k++) {
            if (k == i || k == iu) continue;
            if (in_sizes[k] == in_sizes[i]) { pair[0] = i < k ? i : k; pair[1] = i < k ? k : i; }
        }
    }
    for (int i = 0; i < n_in; i++)
        if (i != iu && i != pair[0] && i != pair[1]) ilen = i;
    if (ilen < 0) { iu = 0; ilen = 1; pair[0] = 2; pair[1] = 3; }

    const float* unary   = (const float*)d_in[iu];
    const int*   lengths = (const int*)d_in[ilen];
    const float* c0      = (const float*)d_in[pair[0]];
    const float* c1      = (const float*)d_in[pair[1]];
    float* out = (float*)d_out;

    const int B = in_sizes[ilen];
    const int T = (int)((long long)in_sizes[iu] / ((long long)B * K_));

    trans_kernel<<<K_, K_>>>(c0, c1);
    sort_kernel<<<1, 1024>>>(lengths, T, B);
    viterbi_kernel<<<NWORK_BLOCKS, 128>>>(unary, lengths, out, T, B);
}

// round 13
// speedup vs baseline: 1.1439x; 1.1439x over previous
#include <cuda_runtime.h>
#include <cstdint>
#include <math.h>

#define GO_TAG 1
#define NEGV   -10000.0f
#define K_     64
#define MAXELEMS_ (1024u * 512u * 64u)
#define ORDER_MAX 65536
#define NWORK_BLOCKS 444   // 3 per SM on 148-SM GB300

// Scratch: alpha history rows 1..len-1 per batch, trans tables, scheduler.
__device__ float g_trans[K_ * K_];    // trans[i][j] = score(i -> j)
__device__ float g_transT[K_ * K_];   // transT[j][i] = trans[i][j]
__device__ float g_alpha[MAXELEMS_];
__device__ int   g_ctr;
__device__ int   g_order[ORDER_MAX];

__device__ __forceinline__ void cp_async16(uint32_t saddr, const void* gptr) {
    asm volatile("cp.async.ca.shared.global [%0], [%1], 16;"
                 :: "r"(saddr), "l"(gptr));
}
__device__ __forceinline__ void cp_commit() {
    asm volatile("cp.async.commit_group;");
}
template <int N>
__device__ __forceinline__ void cp_wait() {
    asm volatile("cp.async.wait_group %0;" :: "n"(N));
}

// One Viterbi step for tag j: max_i(alpha[i] + tr[i][j]) + u. Bit-exact scalar
// form (R10 winner): 16 LDS.128 broadcast, 64 FADD (fma pipe), 63 FMNMX (alu).
__device__ __forceinline__ float vstep(const float* arow_sh,
                                       const float* tr, float u) {
    const float4* av = (const float4*)arow_sh;
    float4 v = av[0];
    float m0 = v.x + tr[0];
    float m1 = v.y + tr[1];
    float m2 = v.z + tr[2];
    float m3 = v.w + tr[3];
    #pragma unroll
    for (int q = 1; q < 16; q++) {
        v = av[q];
        m0 = fmaxf(m0, v.x + tr[4 * q + 0]);
        m1 = fmaxf(m1, v.y + tr[4 * q + 1]);
        m2 = fmaxf(m2, v.z + tr[4 * q + 2]);
        m3 = fmaxf(m3, v.w + tr[4 * q + 3]);
    }
    return fmaxf(fmaxf(m0, m1), fmaxf(m2, m3)) + u;
}

// ---------------------------------------------------------------------------
// Kernel 1: trans = log_softmax(A + mask * NEG, axis=-1) + transpose.
// ---------------------------------------------------------------------------
__global__ void __launch_bounds__(64)
trans_kernel(const float* __restrict__ c0, const float* __restrict__ c1) {
    __shared__ float  s_m[2];
    __shared__ double s_s[2];
    const int r = blockIdx.x;
    const int c = threadIdx.x;
    const int w = c >> 5;
    const int lane = c & 31;

    unsigned u0 = ((const unsigned*)c0)[r * K_ + c];
    const bool c0_is_mask = __syncthreads_and(u0 <= 1u);
    const int*   mask = (const int*)(c0_is_mask ? c0 : c1);
    const float* A    = c0_is_mask ? c1 : c0;

    float x = A[r * K_ + c] + (mask[r * K_ + c] ? NEGV : 0.0f);

    float m = x;
    #pragma unroll
    for (int d = 16; d > 0; d >>= 1) m = fmaxf(m, __shfl_xor_sync(~0u, m, d));
    if (lane == 0) s_m[w] = m;
    __syncthreads();
    m = fmaxf(s_m[0], s_m[1]);

    double e = exp((double)(x - m));
    #pragma unroll
    for (int d = 16; d > 0; d >>= 1) e += __shfl_xor_sync(~0u, e, d);
    if (lane == 0) s_s[w] = e;
    __syncthreads();
    const float l = (float)log(s_s[0] + s_s[1]);

    const float v = (x - m) - l;
    g_trans[r * K_ + c]  = v;
    g_transT[c * K_ + r] = v;
}

// ---------------------------------------------------------------------------
// Kernel 1b: counting-sort sequence indices by DESCENDING length (LPT order).
// ---------------------------------------------------------------------------
__global__ void __launch_bounds__(1024)
sort_kernel(const int* __restrict__ lengths, int T, int B) {
    __shared__ int h[1024];
    __shared__ int h2[1024];
    __shared__ int cur[1024];
    const int tid = threadIdx.x;
    if (tid == 0) g_ctr = 0;
    h[tid] = 0;
    __syncthreads();

    for (int i = tid; i < B; i += 1024) {
        int len = lengths[i]; len = len < 1 ? 1 : (len > T ? T : len);
        int key = T - len; key = key < 0 ? 0 : (key > 1023 ? 1023 : key);
        atomicAdd(&h[key], 1);
    }
    __syncthreads();

    const int cnt = h[tid];
    int* src = h;
    int* dst = h2;
    for (int d = 1; d < 1024; d <<= 1) {
        int v = src[tid];
        if (tid >= d) v += src[tid - d];
        dst[tid] = v;
        __syncthreads();
        int* tmp = src; src = dst; dst = tmp;
    }
    cur[tid] = src[tid] - cnt;   // exclusive prefix = scatter base
    __syncthreads();

    for (int i = tid; i < B; i += 1024) {
        int len = lengths[i]; len = len < 1 ? 1 : (len > T ? T : len);
        int key = T - len; key = key < 0 ? 0 : (key > 1023 ? 1023 : key);
        int pos = atomicAdd(&cur[key], 1);
        if (pos < ORDER_MAX) g_order[pos] = i;
    }
}

// ---------------------------------------------------------------------------
// Kernel 2: PERSISTENT fused Viterbi. 128-thread block = 2 groups of 64;
// each group claims TWO consecutive LPT entries and advances both sequences
// per barrier (2 independent chains/warp, half the barriers per seq-step).
// Backward: warp 0 decodes seq A, warp 1 decodes seq B, in parallel.
// ---------------------------------------------------------------------------
__global__ void __launch_bounds__(128)
viterbi_kernel(const float* __restrict__ unary,
               const int* __restrict__ lengths,
               float* __restrict__ out,
               int T, int B) {
    __shared__ __align__(16) float s_transT[K_ * K_];
    __shared__ __align__(16) float s_alpha[2][2][2][K_];   // [g][seq][buf][j]
    __shared__ __align__(16) float s_u[2][2][2][8][K_];    // [g][seq][buf][s][j]
    __shared__ int s_last[2][2];
    __shared__ int s_idx[2];

    const int tid = threadIdx.x;
    const int g = tid >> 6;
    const int j = tid & 63;
    const int nbar = 1 + g;

    #define GBAR() asm volatile("bar.sync %0, 64;" :: "r"(nbar) : "memory")

    const uint32_t suA =
        (uint32_t)__cvta_generic_to_shared(&s_u[g][0][0][0][0]);
    const uint32_t suB =
        (uint32_t)__cvta_generic_to_shared(&s_u[g][1][0][0][0]);
    const size_t bstride = (size_t)T * K_;

    // One-time: shared transposed table + register transition column.
    {
        const float4* src = (const float4*)g_transT;
        float4* dst = (float4*)s_transT;
        #pragma unroll
        for (int q = 0; q < 8; q++) dst[tid + q * 128] = src[tid + q * 128];
    }
    float tr[K_];
    #pragma unroll
    for (int i = 0; i < K_; i++) tr[i] = g_trans[i * K_ + j];
    __syncthreads();

    // -------------------- persistent work loop --------------------
    for (;;) {
        if (j == 0) s_idx[g] = atomicAdd(&g_ctr, 2);
        GBAR();
        const int idx = s_idx[g];
        if (idx >= B) break;                 // uniform per group
        const int bA = g_order[idx];
        const bool liveB = (idx + 1 < B);
        const int bB = liveB ? g_order[idx + 1] : bA;

        int lenA = lengths[bA];
        lenA = lenA < 1 ? 1 : (lenA > T ? T : lenA);
        int lenB = 0;
        if (liveB) {
            lenB = lengths[bB];
            lenB = lenB < 1 ? 1 : (lenB > T ? T : lenB);
        }
        const int lenmax = lenA > lenB ? lenA : lenB;

        const float* uA = unary + (size_t)bA * bstride;
        const float* uB = unary + (size_t)bB * bstride;
        float* arA = g_alpha + (size_t)bA * bstride;
        float* arB = g_alpha + (size_t)bB * bstride;

        // Prefetch first chunks (steps 1..8 -> rows 0..7, clamped).
        {
            #pragma unroll
            for (int rr = 0; rr < 2; rr++) {
                int l = j + rr * 64;
                int s = l >> 4;
                int c = (l & 15) * 4;
                int row = s; if (row > T - 1) row = T - 1;
                uint32_t soff = (uint32_t)(s * K_ + c) * 4;
                cp_async16(suA + soff, uA + (size_t)row * K_ + c);
                if (liveB) cp_async16(suB + soff, uB + (size_t)row * K_ + c);
            }
            cp_commit();
        }

        const float a0 = (j == GO_TAG) ? 0.0f : NEGV;
        s_alpha[g][0][0][j] = a0;
        s_alpha[g][1][0][j] = a0;
        GBAR();

        // ---------------- forward (shared time counter) ----------------
        int cbuf = 0;
        for (int t0 = 1; t0 <= lenmax; t0 += 8) {
            const bool pfA = (t0 + 8 <= lenA);
            const bool pfB = (t0 + 8 <= lenB);
            #pragma unroll
            for (int rr = 0; rr < 2; rr++) {
                int l = j + rr * 64;
                int s = l >> 4;
                int c = (l & 15) * 4;
                int row = t0 + 7 + s;
                if (row > T - 1) row = T - 1;
                uint32_t soff = (uint32_t)(((cbuf ^ 1) * 8 + s) * K_ + c) * 4;
                if (pfA) cp_async16(suA + soff, uA + (size_t)row * K_ + c);
                if (pfB) cp_async16(suB + soff, uB + (size_t)row * K_ + c);
            }
            cp_commit();      // always commit (possibly empty)
            cp_wait<1>();     // current chunk complete
            GBAR();

            #pragma unroll
            for (int s = 0; s < 8; s++) {
                const int t = t0 + s;
                if (t <= lenmax) {           // uniform per group
                    if (t <= lenA) {         // uniform
                        float a = vstep(s_alpha[g][0][(t - 1) & 1], tr,
                                        s_u[g][0][cbuf][s][j]);
                        s_alpha[g][0][t & 1][j] = a;
                        if (t < lenA) arA[(size_t)t * K_ + j] = a;
                    }
                    if (t <= lenB) {         // uniform
                        float a = vstep(s_alpha[g][1][(t - 1) & 1], tr,
                                        s_u[g][1][cbuf][s][j]);
                        s_alpha[g][1][t & 1][j] = a;
                        if (t < lenB) arB[(size_t)t * K_ + j] = a;
                    }
                    GBAR();
                }
            }
            cbuf ^= 1;
        }

        // last = argmax (first-index tiebreak); thread 0 -> A, thread 32 -> B.
        if (j == 0 || (j == 32 && liveB)) {
            const int q = j >> 5;
            const int len = q ? lenB : lenA;
            const float* af = s_alpha[g][q][len & 1];
            float bv = af[0];
            int bi = 0;
            #pragma unroll
            for (int i = 1; i < K_; i++) {
                if (af[i] > bv) { bv = af[i]; bi = i; }
            }
            s_last[g][q] = bi;
        }
        GBAR();

        // ------------- tails + backward (warp q handles seq q) -------------
        {
            const int q = j >> 5;
            const int lane = j & 31;
            if (q == 0 || liveB) {
                const int len = q ? lenB : lenA;
                const int b = q ? bB : bA;
                float* arow = q ? arB : arA;
                const uint32_t su = q ? suB : suA;
                const int last = s_last[g][q];

                float* ob = out + (size_t)b * T;
                const float lastf = (float)last;
                for (int tau = (len - 1) + lane; tau < T; tau += 32)
                    ob[tau] = lastf;

                if (len >= 2) {
                    int tag = last;
                    #pragma unroll
                    for (int rr = 0; rr < 4; rr++) {
                        int l = lane + rr * 32;
                        int s = l >> 4;
                        int c = (l & 15) * 4;
                        int row = len - 1 - s; if (row < 0) row = 0;
                        cp_async16(su + (uint32_t)(s * K_ + c) * 4,
                                   arow + (size_t)row * K_ + c);
                    }
                    cp_commit();

                    int bbuf = 0;
                    for (int tb = len; tb >= 2; tb -= 8) {
                        if (tb - 8 >= 2) {
                            #pragma unroll
                            for (int rr = 0; rr < 4; rr++) {
                                int l = lane + rr * 32;
                                int s = l >> 4;
                                int c = (l & 15) * 4;
                                int row = tb - 9 - s; if (row < 0) row = 0;
                                cp_async16(su + (uint32_t)(((bbuf ^ 1) * 8 + s) * K_ + c) * 4,
                                           arow + (size_t)row * K_ + c);
                            }
                        }
                        cp_commit();
                        cp_wait<1>();
                        __syncwarp();

                        const int tlo = (tb - 7 > 2) ? tb - 7 : 2;
                        #pragma unroll
                        for (int s = 0; s < 8; s++) {
                            const int t = tb - s;
                            if (t >= tlo) {
                                float2 a = ((const float2*)&s_u[g][q][bbuf][s][0])[lane];
                                float2 tt = ((const float2*)(s_transT + tag * K_))[lane];
                                float c0 = a.x + tt.x;
                                float c1 = a.y + tt.y;
                                float v; int li;
                                if (c0 >= c1) { v = c0; li = 2 * lane; }
                                else          { v = c1; li = 2 * lane + 1; }
                                unsigned bits = __float_as_uint(v);
                                unsigned key = ((int)bits < 0) ? ~bits
                                                               : (bits | 0x80000000u);
                                unsigned mx = __reduce_max_sync(0xffffffffu, key);
                                unsigned sel = (key == mx) ? (unsigned)(K_ - 1 - li) : 0u;
                                unsigned w = __reduce_max_sync(0xffffffffu, sel);
                                tag = (K_ - 1) - (int)w;
                                if (lane == 0) ob[t - 2] = (float)tag;
                            }
                        }
                        bbuf ^= 1;
                    }
                }
            }
        }
        // Protect s_u[g] reuse across claims.
        GBAR();
    }
    #undef GBAR
}

extern "C" void kernel_launch(void* const* d_in, const int* in_sizes, int n_in,
                              void* d_out, int out_size) {
    // ----- identify inputs by SIZE, not position -----
    int iu = 0;
    for (int i = 1; i < n_in; i++)
        if (in_sizes[i] > in_sizes[iu]) iu = i;

    int pair[2] = {-1, -1};
    int ilen = -1;
    for (int i = 0; i < n_in; i++) {
        if (i == iu) continue;
        for (int k = 0; k < n_in; k++) {
            if (k == i || k == iu) continue;
            if (in_sizes[k] == in_sizes[i]) { pair[0] = i < k ? i : k; pair[1] = i < k ? k : i; }
        }
    }
    for (int i = 0; i < n_in; i++)
        if (i != iu && i != pair[0] && i != pair[1]) ilen = i;
    if (ilen < 0) { iu = 0; ilen = 1; pair[0] = 2; pair[1] = 3; }

    const float* unary   = (const float*)d_in[iu];
    const int*   lengths = (const int*)d_in[ilen];
    const float* c0      = (const float*)d_in[pair[0]];
    const float* c1      = (const float*)d_in[pair[1]];
    float* out = (float*)d_out;

    const int B = in_sizes[ilen];
    const int T = (int)((long long)in_sizes[iu] / ((long long)B * K_));

    trans_kernel<<<K_, K_>>>(c0, c1);
    sort_kernel<<<1, 1024>>>(lengths, T, B);
    viterbi_kernel<<<NWORK_BLOCKS, 128>>>(unary, lengths, out, T, B);
}

// round 14
// speedup vs baseline: 1.4045x; 1.2278x over previous
#include <cuda_runtime.h>
#include <cstdint>
#include <math.h>

#define GO_TAG 1
#define NEGV   -10000.0f
#define K_     64
#define MAXELEMS_ (1024u * 512u * 64u)

// Scratch: alpha history rows 1..len-1 per batch, trans tables.
__device__ float g_trans[K_ * K_];    // trans[i][j] = score(i -> j)
__device__ float g_transT[K_ * K_];   // transT[j][i] = trans[i][j]
__device__ float g_alpha[MAXELEMS_];

__device__ __forceinline__ void cp_async16(uint32_t saddr, const void* gptr) {
    asm volatile("cp.async.ca.shared.global [%0], [%1], 16;"
                 :: "r"(saddr), "l"(gptr));
}
__device__ __forceinline__ void cp_commit() {
    asm volatile("cp.async.commit_group;");
}
template <int N>
__device__ __forceinline__ void cp_wait() {
    asm volatile("cp.async.wait_group %0;" :: "n"(N));
}

// ---------------------------------------------------------------------------
// Kernel 1: trans = log_softmax(A + mask * NEG, axis=-1) + transpose.
// ---------------------------------------------------------------------------
__global__ void __launch_bounds__(64)
trans_kernel(const float* __restrict__ c0, const float* __restrict__ c1) {
    __shared__ float  s_m[2];
    __shared__ double s_s[2];
    const int r = blockIdx.x;
    const int c = threadIdx.x;
    const int w = c >> 5;
    const int lane = c & 31;

    unsigned u0 = ((const unsigned*)c0)[r * K_ + c];
    const bool c0_is_mask = __syncthreads_and(u0 <= 1u);
    const int*   mask = (const int*)(c0_is_mask ? c0 : c1);
    const float* A    = c0_is_mask ? c1 : c0;

    float x = A[r * K_ + c] + (mask[r * K_ + c] ? NEGV : 0.0f);

    float m = x;
    #pragma unroll
    for (int d = 16; d > 0; d >>= 1) m = fmaxf(m, __shfl_xor_sync(~0u, m, d));
    if (lane == 0) s_m[w] = m;
    __syncthreads();
    m = fmaxf(s_m[0], s_m[1]);

    double e = exp((double)(x - m));
    #pragma unroll
    for (int d = 16; d > 0; d >>= 1) e += __shfl_xor_sync(~0u, e, d);
    if (lane == 0) s_s[w] = e;
    __syncthreads();
    const float l = (float)log(s_s[0] + s_s[1]);

    const float v = (x - m) - l;
    g_trans[r * K_ + c]  = v;
    g_transT[c * K_ + r] = v;
}

// ---------------------------------------------------------------------------
// Kernel 2: ONE WARP PER SEQUENCE, barrier-free. Thread k owns tags 2k,2k+1
// with both trans columns in registers (128 regs; NO launch-bounds reg cap).
// Alphas exchanged through warp-private smem with __syncwarp only.
// cp.async double-buffered staging for unary (fwd) and alpha history (bwd).
// Block = 4 warps = 4 independent sequences; grid = ceil(B/4).
// ---------------------------------------------------------------------------
__global__ void __launch_bounds__(128)
viterbi_kernel(const float* __restrict__ unary,
               const int* __restrict__ lengths,
               float* __restrict__ out,
               int T, int B) {
    __shared__ __align__(16) float s_transT[K_ * K_];   // 16KB, backward
    __shared__ __align__(16) float s_alpha[4][2][K_];   // [warp][buf][j]
    __shared__ __align__(16) float s_u[4][2][8][K_];    // [warp][buf][s][j]

    const int tid = threadIdx.x;
    const int w = tid >> 5;
    const int lane = tid & 31;

    // Cooperative transT copy (for backward), then one block sync.
    {
        const float4* src = (const float4*)g_transT;
        float4* dst = (float4*)s_transT;
        #pragma unroll
        for (int q = 0; q < 8; q++) dst[tid + q * 128] = src[tid + q * 128];
    }
    // Trans columns for tags j0 = 2*lane, j1 = 2*lane+1 (registers).
    float tr0[K_], tr1[K_];
    #pragma unroll
    for (int i = 0; i < K_; i++) {
        tr0[i] = g_trans[i * K_ + 2 * lane];
        tr1[i] = g_trans[i * K_ + 2 * lane + 1];
    }
    __syncthreads();   // s_transT visible to all warps (no block syncs after)

    const int b = blockIdx.x * 4 + w;
    if (b >= B) return;

    int len = lengths[b];
    len = len < 1 ? 1 : (len > T ? T : len);

    const size_t bstride = (size_t)T * K_;
    const float* ub = unary + (size_t)b * bstride;
    float* arow = g_alpha + (size_t)b * bstride;
    float* ob = out + (size_t)b * T;

    const uint32_t su_base =
        (uint32_t)__cvta_generic_to_shared(&s_u[w][0][0][0]);

    // ---- prefetch first unary chunk (steps 1..8 -> rows 0..7, clamped) ----
    #pragma unroll
    for (int rr = 0; rr < 4; rr++) {
        int l = lane + rr * 32;
        int s = l >> 4;
        int c = (l & 15) * 4;
        int row = s; if (row > T - 1) row = T - 1;
        cp_async16(su_base + (uint32_t)(s * K_ + c) * 4,
                   ub + (size_t)row * K_ + c);
    }
    cp_commit();

    // GO frame.
    {
        float a0 = (2 * lane == GO_TAG) ? 0.0f : NEGV;
        float a1 = (2 * lane + 1 == GO_TAG) ? 0.0f : NEGV;
        ((float2*)s_alpha[w][0])[lane] = make_float2(a0, a1);
    }
    __syncwarp();

    // -------------------- forward --------------------
    int cbuf = 0;
    for (int t0 = 1; t0 <= len; t0 += 8) {
        if (t0 + 8 <= len) {
            #pragma unroll
            for (int rr = 0; rr < 4; rr++) {
                int l = lane + rr * 32;
                int s = l >> 4;
                int c = (l & 15) * 4;
                int row = t0 + 7 + s;
                if (row > T - 1) row = T - 1;
                cp_async16(su_base + (uint32_t)(((cbuf ^ 1) * 8 + s) * K_ + c) * 4,
                           ub + (size_t)row * K_ + c);
            }
        }
        cp_commit();      // always commit (possibly empty)
        cp_wait<1>();     // current chunk complete (per-thread)
        __syncwarp();     // cross-lane visibility of staged data

        #pragma unroll
        for (int s = 0; s < 8; s++) {
            const int t = t0 + s;
            if (t <= len) {                  // uniform per warp
                const float2 u = ((const float2*)&s_u[w][cbuf][s][0])[lane];
                const float4* av = (const float4*)s_alpha[w][(t - 1) & 1];
                float4 v = av[0];
                float p00 = v.x + tr0[0], p01 = v.y + tr0[1];
                float p02 = v.z + tr0[2], p03 = v.w + tr0[3];
                float p10 = v.x + tr1[0], p11 = v.y + tr1[1];
                float p12 = v.z + tr1[2], p13 = v.w + tr1[3];
                #pragma unroll
                for (int q = 1; q < 16; q++) {
                    v = av[q];
                    p00 = fmaxf(p00, v.x + tr0[4 * q + 0]);
                    p01 = fmaxf(p01, v.y + tr0[4 * q + 1]);
                    p02 = fmaxf(p02, v.z + tr0[4 * q + 2]);
                    p03 = fmaxf(p03, v.w + tr0[4 * q + 3]);
                    p10 = fmaxf(p10, v.x + tr1[4 * q + 0]);
                    p11 = fmaxf(p11, v.y + tr1[4 * q + 1]);
                    p12 = fmaxf(p12, v.z + tr1[4 * q + 2]);
                    p13 = fmaxf(p13, v.w + tr1[4 * q + 3]);
                }
                float A0 = fmaxf(fmaxf(p00, p01), fmaxf(p02, p03)) + u.x;
                float A1 = fmaxf(fmaxf(p10, p11), fmaxf(p12, p13)) + u.y;
                ((float2*)s_alpha[w][t & 1])[lane] = make_float2(A0, A1);
                if (t < len)
                    ((float2*)(arow + (size_t)t * K_))[lane] =
                        make_float2(A0, A1);  // rows 1..len-1
                __syncwarp();
            }
        }
        cbuf ^= 1;
    }

    // last = argmax_j(final alpha), first-index tiebreak (exact, lane 0).
    int last;
    {
        int bi = 0;
        if (lane == 0) {
            const float* af = s_alpha[w][len & 1];
            float bv = af[0];
            #pragma unroll
            for (int i = 1; i < K_; i++) {
                if (af[i] > bv) { bv = af[i]; bi = i; }
            }
        }
        last = __shfl_sync(0xffffffffu, bi, 0);
    }

    // Output positions tau >= len-1 all equal `last`.
    const float lastf = (float)last;
    for (int tau = (len - 1) + lane; tau < T; tau += 32) ob[tau] = lastf;

    // -------------------- backward --------------------
    if (len >= 2) {
        int tag = last;

        #pragma unroll
        for (int rr = 0; rr < 4; rr++) {
            int l = lane + rr * 32;
            int s = l >> 4;
            int c = (l & 15) * 4;
            int row = len - 1 - s; if (row < 0) row = 0;
            cp_async16(su_base + (uint32_t)(s * K_ + c) * 4,
                       arow + (size_t)row * K_ + c);
        }
        cp_commit();

        int bbuf = 0;
        for (int tb = len; tb >= 2; tb -= 8) {
            if (tb - 8 >= 2) {
                #pragma unroll
                for (int rr = 0; rr < 4; rr++) {
                    int l = lane + rr * 32;
                    int s = l >> 4;
                    int c = (l & 15) * 4;
                    int row = tb - 9 - s; if (row < 0) row = 0;
                    cp_async16(su_base + (uint32_t)(((bbuf ^ 1) * 8 + s) * K_ + c) * 4,
                               arow + (size_t)row * K_ + c);
                }
            }
            cp_commit();
            cp_wait<1>();
            __syncwarp();

            const int tlo = (tb - 7 > 2) ? tb - 7 : 2;
            #pragma unroll
            for (int s = 0; s < 8; s++) {
                const int t = tb - s;
                if (t >= tlo) {
                    float2 a = ((const float2*)&s_u[w][bbuf][s][0])[lane];
                    float2 tt = ((const float2*)(s_transT + tag * K_))[lane];
                    float c0 = a.x + tt.x;
                    float c1 = a.y + tt.y;
                    float v; int li;
                    if (c0 >= c1) { v = c0; li = 2 * lane; }
                    else          { v = c1; li = 2 * lane + 1; }
                    unsigned bits = __float_as_uint(v);
                    unsigned key = ((int)bits < 0) ? ~bits : (bits | 0x80000000u);
                    unsigned mx = __reduce_max_sync(0xffffffffu, key);
                    unsigned sel = (key == mx) ? (unsigned)(K_ - 1 - li) : 0u;
                    unsigned ww = __reduce_max_sync(0xffffffffu, sel);
                    tag = (K_ - 1) - (int)ww;
                    if (lane == 0) ob[t - 2] = (float)tag;
                }
            }
            bbuf ^= 1;
        }
    }
}

extern "C" void kernel_launch(void* const* d_in, const int* in_sizes, int n_in,
                              void* d_out, int out_size) {
    // ----- identify inputs by SIZE, not position -----
    int iu = 0;
    for (int i = 1; i < n_in; i++)
        if (in_sizes[i] > in_sizes[iu]) iu = i;

    int pair[2] = {-1, -1};
    int ilen = -1;
    for (int i = 0; i < n_in; i++) {
        if (i == iu) continue;
        for (int k = 0; k < n_in; k++) {
            if (k == i || k == iu) continue;
            if (in_sizes[k] == in_sizes[i]) { pair[0] = i < k ? i : k; pair[1] = i < k ? k : i; }
        }
    }
    for (int i = 0; i < n_in; i++)
        if (i != iu && i != pair[0] && i != pair[1]) ilen = i;
    if (ilen < 0) { iu = 0; ilen = 1; pair[0] = 2; pair[1] = 3; }

    const float* unary   = (const float*)d_in[iu];
    const int*   lengths = (const int*)d_in[ilen];
    const float* c0      = (const float*)d_in[pair[0]];
    const float* c1      = (const float*)d_in[pair[1]];
    float* out = (float*)d_out;

    const int B = in_sizes[ilen];
    const int T = (int)((long long)in_sizes[iu] / ((long long)B * K_));

    trans_kernel<<<K_, K_>>>(c0, c1);
    viterbi_kernel<<<(B + 3) / 4, 128>>>(unary, lengths, out, T, B);
}

// round 15
// speedup vs baseline: 1.5058x; 1.0721x over previous
#include <cuda_runtime.h>
#include <cstdint>
#include <math.h>

#define GO_TAG 1
#define NEGV   -10000.0f
#define K_     64
#define MAXELEMS_ (1024u * 512u * 64u)
#define ORDER_MAX 65536
#define NWORK_BLOCKS 592   // 4/SM if regs <= 128; extra blocks exit instantly

// Scratch: alpha history rows 1..len-1 per batch, trans tables, scheduler.
__device__ float g_trans[K_ * K_];    // trans[i][j] = score(i -> j)
__device__ float g_transT[K_ * K_];   // transT[j][i] = trans[i][j]
__device__ float g_alpha[MAXELEMS_];
__device__ int   g_ctr;
__device__ int   g_order[ORDER_MAX];

__device__ __forceinline__ void cp_async16(uint32_t saddr, const void* gptr) {
    asm volatile("cp.async.ca.shared.global [%0], [%1], 16;"
                 :: "r"(saddr), "l"(gptr));
}
__device__ __forceinline__ void cp_commit() {
    asm volatile("cp.async.commit_group;");
}
template <int N>
__device__ __forceinline__ void cp_wait() {
    asm volatile("cp.async.wait_group %0;" :: "n"(N));
}

// ---------------------------------------------------------------------------
// Kernel 1: trans = log_softmax(A + mask * NEG, axis=-1) + transpose.
// ---------------------------------------------------------------------------
__global__ void __launch_bounds__(64)
trans_kernel(const float* __restrict__ c0, const float* __restrict__ c1) {
    __shared__ float  s_m[2];
    __shared__ double s_s[2];
    const int r = blockIdx.x;
    const int c = threadIdx.x;
    const int w = c >> 5;
    const int lane = c & 31;

    unsigned u0 = ((const unsigned*)c0)[r * K_ + c];
    const bool c0_is_mask = __syncthreads_and(u0 <= 1u);
    const int*   mask = (const int*)(c0_is_mask ? c0 : c1);
    const float* A    = c0_is_mask ? c1 : c0;

    float x = A[r * K_ + c] + (mask[r * K_ + c] ? NEGV : 0.0f);

    float m = x;
    #pragma unroll
    for (int d = 16; d > 0; d >>= 1) m = fmaxf(m, __shfl_xor_sync(~0u, m, d));
    if (lane == 0) s_m[w] = m;
    __syncthreads();
    m = fmaxf(s_m[0], s_m[1]);

    double e = exp((double)(x - m));
    #pragma unroll
    for (int d = 16; d > 0; d >>= 1) e += __shfl_xor_sync(~0u, e, d);
    if (lane == 0) s_s[w] = e;
    __syncthreads();
    const float l = (float)log(s_s[0] + s_s[1]);

    const float v = (x - m) - l;
    g_trans[r * K_ + c]  = v;
    g_transT[c * K_ + r] = v;
}

// ---------------------------------------------------------------------------
// Kernel 1b: counting-sort sequence indices by DESCENDING length (LPT order).
// ---------------------------------------------------------------------------
__global__ void __launch_bounds__(1024)
sort_kernel(const int* __restrict__ lengths, int T, int B) {
    __shared__ int h[1024];
    __shared__ int h2[1024];
    __shared__ int cur[1024];
    const int tid = threadIdx.x;
    if (tid == 0) g_ctr = 0;
    h[tid] = 0;
    __syncthreads();

    for (int i = tid; i < B; i += 1024) {
        int len = lengths[i]; len = len < 1 ? 1 : (len > T ? T : len);
        int key = T - len; key = key < 0 ? 0 : (key > 1023 ? 1023 : key);
        atomicAdd(&h[key], 1);
    }
    __syncthreads();

    const int cnt = h[tid];
    int* src = h;
    int* dst = h2;
    for (int d = 1; d < 1024; d <<= 1) {
        int v = src[tid];
        if (tid >= d) v += src[tid - d];
        dst[tid] = v;
        __syncthreads();
        int* tmp = src; src = dst; dst = tmp;
    }
    cur[tid] = src[tid] - cnt;   // exclusive prefix = scatter base
    __syncthreads();

    for (int i = tid; i < B; i += 1024) {
        int len = lengths[i]; len = len < 1 ? 1 : (len > T ? T : len);
        int key = T - len; key = key < 0 ? 0 : (key > 1023 ? 1023 : key);
        int pos = atomicAdd(&cur[key], 1);
        if (pos < ORDER_MAX) g_order[pos] = i;
    }
}

// ---------------------------------------------------------------------------
// Kernel 2: PERSISTENT fused Viterbi (R10 winner body). 128-thread block =
// 2 independent 64-thread groups claiming sequences (LPT order). All offsets
// 32-bit (max 2^25 elems) to trim register pressure below the 128-reg /
// 4-blocks-per-SM threshold. NO register cap (R12 proved caps cause spills).
// ---------------------------------------------------------------------------
__global__ void __launch_bounds__(128)
viterbi_kernel(const float* __restrict__ unary,
               const int* __restrict__ lengths,
               float* __restrict__ out,
               int T, int B) {
    __shared__ __align__(16) float s_transT[K_ * K_];
    __shared__ __align__(16) float s_alpha[2][2][K_];   // [g][buf][j]
    __shared__ __align__(16) float s_u[2][2][8][K_];    // [g][buf][s][j]
    __shared__ int s_last[2];
    __shared__ int s_idx[2];

    const int tid = threadIdx.x;
    const int g = tid >> 6;
    const int j = tid & 63;
    const int nbar = 1 + g;

    #define GBAR() asm volatile("bar.sync %0, 64;" :: "r"(nbar) : "memory")

    const uint32_t su_base =
        (uint32_t)__cvta_generic_to_shared(&s_u[g][0][0][0]);
    const unsigned bstride = (unsigned)T * K_;   // <= 2^25, fits 32-bit

    // One-time: shared transposed table + register transition column.
    {
        const float4* src = (const float4*)g_transT;
        float4* dst = (float4*)s_transT;
        #pragma unroll
        for (int q = 0; q < 8; q++) dst[tid + q * 128] = src[tid + q * 128];
    }
    float tr[K_];
    #pragma unroll
    for (int i = 0; i < K_; i++) tr[i] = g_trans[i * K_ + j];
    __syncthreads();

    // -------------------- persistent work loop --------------------
    for (;;) {
        if (j == 0) s_idx[g] = atomicAdd(&g_ctr, 1);
        GBAR();
        const int idx = s_idx[g];
        if (idx >= B) break;                 // uniform per group
        const int b = g_order[idx];

        int len = lengths[b];
        len = len < 1 ? 1 : (len > T ? T : len);
        const float* ub = unary + (unsigned)b * bstride;
        float* arow = g_alpha + (unsigned)b * bstride;

        // Prefetch first unary chunk (steps 1..8 -> rows 0..7, clamped).
        {
            #pragma unroll
            for (int rr = 0; rr < 2; rr++) {
                int l = j + rr * 64;
                int s = l >> 4;
                int c = (l & 15) * 4;
                unsigned row = (unsigned)(s > T - 1 ? T - 1 : s);
                cp_async16(su_base + (uint32_t)(s * K_ + c) * 4,
                           ub + row * K_ + c);
            }
            cp_commit();
        }

        s_alpha[g][0][j] = (j == GO_TAG) ? 0.0f : NEGV;
        GBAR();

        // ---------------- forward ----------------
        int cbuf = 0;
        for (int t0 = 1; t0 <= len; t0 += 8) {
            if (t0 + 8 <= len) {
                #pragma unroll
                for (int rr = 0; rr < 2; rr++) {
                    int l = j + rr * 64;
                    int s = l >> 4;
                    int c = (l & 15) * 4;
                    int row = t0 + 7 + s;
                    if (row > T - 1) row = T - 1;
                    cp_async16(su_base + (uint32_t)(((cbuf ^ 1) * 8 + s) * K_ + c) * 4,
                               ub + (unsigned)row * K_ + c);
                }
            }
            cp_commit();      // always commit (possibly empty)
            cp_wait<1>();     // current chunk complete
            GBAR();

            const int tend = (t0 + 7 < len) ? t0 + 7 : len;
            #pragma unroll
            for (int s = 0; s < 8; s++) {
                const int t = t0 + s;
                if (t <= tend) {             // uniform per group
                    const float u = s_u[g][cbuf][s][j];
                    const float4* av = (const float4*)s_alpha[g][(t - 1) & 1];
                    float4 v = av[0];
                    float m0 = v.x + tr[0];
                    float m1 = v.y + tr[1];
                    float m2 = v.z + tr[2];
                    float m3 = v.w + tr[3];
                    #pragma unroll
                    for (int q = 1; q < 16; q++) {
                        v = av[q];
                        m0 = fmaxf(m0, v.x + tr[4 * q + 0]);
                        m1 = fmaxf(m1, v.y + tr[4 * q + 1]);
                        m2 = fmaxf(m2, v.z + tr[4 * q + 2]);
                        m3 = fmaxf(m3, v.w + tr[4 * q + 3]);
                    }
                    float a = fmaxf(fmaxf(m0, m1), fmaxf(m2, m3)) + u;
                    s_alpha[g][t & 1][j] = a;
                    if (t < len)
                        arow[(unsigned)t * K_ + j] = a;   // rows 1..len-1
                    GBAR();
                }
            }
            cbuf ^= 1;
        }

        // last = argmax_j(final alpha), first-index tiebreak (exact scan).
        if (j == 0) {
            const float* af = s_alpha[g][len & 1];
            float bv = af[0];
            int bi = 0;
            #pragma unroll
            for (int i = 1; i < K_; i++) {
                if (af[i] > bv) { bv = af[i]; bi = i; }
            }
            s_last[g] = bi;
        }
        GBAR();
        const int last = s_last[g];

        // Output positions tau >= len-1 all equal `last`.
        float* ob = out + (unsigned)b * (unsigned)T;
        const float lastf = (float)last;
        for (int tau = (len - 1) + j; tau < T; tau += K_) ob[tau] = lastf;

        // ---------------- backward (warp 0 of group) ----------------
        if (j < 32 && len >= 2) {
            const int lane = j;
            int tag = last;

            #pragma unroll
            for (int rr = 0; rr < 4; rr++) {
                int l = lane + rr * 32;
                int s = l >> 4;
                int c = (l & 15) * 4;
                int row = len - 1 - s; if (row < 0) row = 0;
                cp_async16(su_base + (uint32_t)(s * K_ + c) * 4,
                           arow + (unsigned)row * K_ + c);
            }
            cp_commit();

            int bbuf = 0;
            for (int tb = len; tb >= 2; tb -= 8) {
                if (tb - 8 >= 2) {
                    #pragma unroll
                    for (int rr = 0; rr < 4; rr++) {
                        int l = lane + rr * 32;
                        int s = l >> 4;
                        int c = (l & 15) * 4;
                        int row = tb - 9 - s; if (row < 0) row = 0;
                        cp_async16(su_base + (uint32_t)(((bbuf ^ 1) * 8 + s) * K_ + c) * 4,
                                   arow + (unsigned)row * K_ + c);
                    }
                }
                cp_commit();
                cp_wait<1>();
                __syncwarp();

                const int tlo = (tb - 7 > 2) ? tb - 7 : 2;
                #pragma unroll
                for (int s = 0; s < 8; s++) {
                    const int t = tb - s;
                    if (t >= tlo) {
                        float2 a = ((const float2*)&s_u[g][bbuf][s][0])[lane];
                        float2 tt = ((const float2*)(s_transT + tag * K_))[lane];
                        float c0 = a.x + tt.x;
                        float c1 = a.y + tt.y;
                        float v; int li;
                        if (c0 >= c1) { v = c0; li = 2 * lane; }
                        else          { v = c1; li = 2 * lane + 1; }
                        unsigned bits = __float_as_uint(v);
                        unsigned key = ((int)bits < 0) ? ~bits
                                                       : (bits | 0x80000000u);
                        unsigned mx = __reduce_max_sync(0xffffffffu, key);
                        unsigned sel = (key == mx) ? (unsigned)(K_ - 1 - li) : 0u;
                        unsigned w = __reduce_max_sync(0xffffffffu, sel);
                        tag = (K_ - 1) - (int)w;
                        if (lane == 0) ob[t - 2] = (float)tag;
                    }
                }
                bbuf ^= 1;
            }
        }
        // Protect s_u[g] reuse across sequences.
        GBAR();
    }
    #undef GBAR
}

extern "C" void kernel_launch(void* const* d_in, const int* in_sizes, int n_in,
                              void* d_out, int out_size) {
    // ----- identify inputs by SIZE, not position -----
    int iu = 0;
    for (int i = 1; i < n_in; i++)
        if (in_sizes[i] > in_sizes[iu]) iu = i;

    int pair[2] = {-1, -1};
    int ilen = -1;
    for (int i = 0; i < n_in; i++) {
        if (i == iu) continue;
        for (int k = 0; k < n_in; k++) {
            if (k == i || k == iu) continue;
            if (in_sizes[k] == in_sizes[i]) { pair[0] = i < k ? i : k; pair[1] = i < k ? k : i; }
        }
    }
    for (int i = 0; i < n_in; i++)
        if (i != iu && i != pair[0] && i != pair[1]) ilen = i;
    if (ilen < 0) { iu = 0; ilen = 1; pair[0] = 2; pair[1] = 3; }

    const float* unary   = (const float*)d_in[iu];
    const int*   lengths = (const int*)d_in[ilen];
    const float* c0      = (const float*)d_in[pair[0]];
    const float* c1      = (const float*)d_in[pair[1]];
    float* out = (float*)d_out;

    const int B = in_sizes[ilen];
    const int T = (int)((long long)in_sizes[iu] / ((long long)B * K_));

    trans_kernel<<<K_, K_>>>(c0, c1);
    sort_kernel<<<1, 1024>>>(lengths, T, B);
    viterbi_kernel<<<NWORK_BLOCKS, 128>>>(unary, lengths, out, T, B);
}

// round 16
// speedup vs baseline: 1.6271x; 1.0806x over previous
#include <cuda_runtime.h>
#include <cstdint>
#include <math.h>

#define GO_TAG 1
#define NEGV   -10000.0f
#define K_     64
#define MAXELEMS_ (1024u * 512u * 64u)
#define ORDER_MAX 65536
#define NWORK_BLOCKS 444   // 3 per SM on 148-SM GB300 (measured optimum)

// Scratch: alpha history rows 1..len-1 per batch, trans tables, scheduler.
__device__ float g_trans[K_ * K_];    // trans[i][j] = score(i -> j)
__device__ float g_transT[K_ * K_];   // transT[j][i] = trans[i][j]
__device__ float g_alpha[MAXELEMS_];
__device__ int   g_ctr;
__device__ int   g_order[ORDER_MAX];

__device__ __forceinline__ void cp_async16(uint32_t saddr, const void* gptr) {
    asm volatile("cp.async.ca.shared.global [%0], [%1], 16;"
                 :: "r"(saddr), "l"(gptr));
}
__device__ __forceinline__ void cp_commit() {
    asm volatile("cp.async.commit_group;");
}
template <int N>
__device__ __forceinline__ void cp_wait() {
    asm volatile("cp.async.wait_group %0;" :: "n"(N));
}

// ---------------------------------------------------------------------------
// Fused prelude: blocks 0..63 -> log_softmax row r (64 active lanes);
// block 64 -> LPT counting sort of sequence indices + counter reset.
// ---------------------------------------------------------------------------
__global__ void __launch_bounds__(1024)
prelude_kernel(const float* __restrict__ c0, const float* __restrict__ c1,
               const int* __restrict__ lengths, int T, int B) {
    const int tid = threadIdx.x;

    if (blockIdx.x < 64) {
        // ---------- trans row ----------
        __shared__ float  s_m[2];
        __shared__ double s_s[2];
        const int r = blockIdx.x;
        const int c = tid;                 // only c < 64 does work
        const bool active = (c < K_);
        const int w = c >> 5;              // 0 or 1 for active threads
        const int lane = c & 31;

        unsigned u0 = active ? ((const unsigned*)c0)[r * K_ + c] : 0u;
        const bool c0_is_mask = __syncthreads_and(u0 <= 1u);
        const int*   mask = (const int*)(c0_is_mask ? c0 : c1);
        const float* A    = c0_is_mask ? c1 : c0;

        if (active) {
            float x = A[r * K_ + c] + (mask[r * K_ + c] ? NEGV : 0.0f);

            float m = x;
            #pragma unroll
            for (int d = 16; d > 0; d >>= 1)
                m = fmaxf(m, __shfl_xor_sync(~0u, m, d));
            if (lane == 0) s_m[w] = m;
        }
        __syncthreads();
        if (active) {
            float x = A[r * K_ + c] + (mask[r * K_ + c] ? NEGV : 0.0f);
            float m = fmaxf(s_m[0], s_m[1]);

            double e = exp((double)(x - m));
            #pragma unroll
            for (int d = 16; d > 0; d >>= 1) e += __shfl_xor_sync(~0u, e, d);
            if (lane == 0) s_s[w] = e;
        }
        __syncthreads();
        if (active) {
            float x = A[r * K_ + c] + (mask[r * K_ + c] ? NEGV : 0.0f);
            float m = fmaxf(s_m[0], s_m[1]);
            const float l = (float)log(s_s[0] + s_s[1]);
            const float v = (x - m) - l;
            g_trans[r * K_ + c]  = v;
            g_transT[c * K_ + r] = v;
        }
    } else {
        // ---------- LPT counting sort ----------
        __shared__ int h[1024];
        __shared__ int h2[1024];
        __shared__ int cur[1024];
        if (tid == 0) g_ctr = 0;
        h[tid] = 0;
        __syncthreads();

        for (int i = tid; i < B; i += 1024) {
            int len = lengths[i]; len = len < 1 ? 1 : (len > T ? T : len);
            int key = T - len; key = key < 0 ? 0 : (key > 1023 ? 1023 : key);
            atomicAdd(&h[key], 1);
        }
        __syncthreads();

        const int cnt = h[tid];
        int* src = h;
        int* dst = h2;
        for (int d = 1; d < 1024; d <<= 1) {
            int v = src[tid];
            if (tid >= d) v += src[tid - d];
            dst[tid] = v;
            __syncthreads();
            int* tmp = src; src = dst; dst = tmp;
        }
        cur[tid] = src[tid] - cnt;   // exclusive prefix = scatter base
        __syncthreads();

        for (int i = tid; i < B; i += 1024) {
            int len = lengths[i]; len = len < 1 ? 1 : (len > T ? T : len);
            int key = T - len; key = key < 0 ? 0 : (key > 1023 ? 1023 : key);
            int pos = atomicAdd(&cur[key], 1);
            if (pos < ORDER_MAX) g_order[pos] = i;
        }
    }
}

// ---------------------------------------------------------------------------
// Kernel 2: PERSISTENT fused Viterbi (R10 winner body, unchanged inner loop).
// 128-thread block = 2 independent 64-thread groups claiming sequences in
// LPT order. Tail output moved to warp 1 (overlaps warp 0's backward).
// ---------------------------------------------------------------------------
__global__ void __launch_bounds__(128)
viterbi_kernel(const float* __restrict__ unary,
               const int* __restrict__ lengths,
               float* __restrict__ out,
               int T, int B) {
    __shared__ __align__(16) float s_transT[K_ * K_];
    __shared__ __align__(16) float s_alpha[2][2][K_];   // [g][buf][j]
    __shared__ __align__(16) float s_u[2][2][8][K_];    // [g][buf][s][j]
    __shared__ int s_last[2];
    __shared__ int s_idx[2];

    const int tid = threadIdx.x;
    const int g = tid >> 6;
    const int j = tid & 63;
    const int nbar = 1 + g;

    #define GBAR() asm volatile("bar.sync %0, 64;" :: "r"(nbar) : "memory")

    const uint32_t su_base =
        (uint32_t)__cvta_generic_to_shared(&s_u[g][0][0][0]);
    const size_t bstride = (size_t)T * K_;

    // One-time: shared transposed table + register transition column.
    {
        const float4* src = (const float4*)g_transT;
        float4* dst = (float4*)s_transT;
        #pragma unroll
        for (int q = 0; q < 8; q++) dst[tid + q * 128] = src[tid + q * 128];
    }
    float tr[K_];
    #pragma unroll
    for (int i = 0; i < K_; i++) tr[i] = g_trans[i * K_ + j];
    __syncthreads();

    // -------------------- persistent work loop --------------------
    for (;;) {
        if (j == 0) s_idx[g] = atomicAdd(&g_ctr, 1);
        GBAR();
        const int idx = s_idx[g];
        if (idx >= B) break;                 // uniform per group
        const int b = g_order[idx];

        int len = lengths[b];
        len = len < 1 ? 1 : (len > T ? T : len);
        const float* ub = unary + (size_t)b * bstride;
        float* arow = g_alpha + (size_t)b * bstride;

        // Prefetch first unary chunk (steps 1..8 -> rows 0..7, clamped).
        {
            #pragma unroll
            for (int rr = 0; rr < 2; rr++) {
                int l = j + rr * 64;
                int s = l >> 4;
                int c = (l & 15) * 4;
                int row = s; if (row > T - 1) row = T - 1;
                cp_async16(su_base + (uint32_t)(s * K_ + c) * 4,
                           ub + (size_t)row * K_ + c);
            }
            cp_commit();
        }

        s_alpha[g][0][j] = (j == GO_TAG) ? 0.0f : NEGV;
        GBAR();

        // ---------------- forward ----------------
        int cbuf = 0;
        for (int t0 = 1; t0 <= len; t0 += 8) {
            if (t0 + 8 <= len) {
                #pragma unroll
                for (int rr = 0; rr < 2; rr++) {
                    int l = j + rr * 64;
                    int s = l >> 4;
                    int c = (l & 15) * 4;
                    int row = t0 + 7 + s;
                    if (row > T - 1) row = T - 1;
                    cp_async16(su_base + (uint32_t)(((cbuf ^ 1) * 8 + s) * K_ + c) * 4,
                               ub + (size_t)row * K_ + c);
                }
            }
            cp_commit();      // always commit (possibly empty)
            cp_wait<1>();     // current chunk complete
            GBAR();

            const int tend = (t0 + 7 < len) ? t0 + 7 : len;
            #pragma unroll
            for (int s = 0; s < 8; s++) {
                const int t = t0 + s;
                if (t <= tend) {             // uniform per group
                    const float u = s_u[g][cbuf][s][j];
                    const float4* av = (const float4*)s_alpha[g][(t - 1) & 1];
                    float4 v = av[0];
                    float m0 = v.x + tr[0];
                    float m1 = v.y + tr[1];
                    float m2 = v.z + tr[2];
                    float m3 = v.w + tr[3];
                    #pragma unroll
                    for (int q = 1; q < 16; q++) {
                        v = av[q];
                        m0 = fmaxf(m0, v.x + tr[4 * q + 0]);
                        m1 = fmaxf(m1, v.y + tr[4 * q + 1]);
                        m2 = fmaxf(m2, v.z + tr[4 * q + 2]);
                        m3 = fmaxf(m3, v.w + tr[4 * q + 3]);
                    }
                    float a = fmaxf(fmaxf(m0, m1), fmaxf(m2, m3)) + u;
                    s_alpha[g][t & 1][j] = a;
                    if (t < len) arow[(size_t)t * K_ + j] = a;  // rows 1..len-1
                    GBAR();
                }
            }
            cbuf ^= 1;
        }

        // last = argmax_j(final alpha), first-index tiebreak (exact scan).
        if (j == 0) {
            const float* af = s_alpha[g][len & 1];
            float bv = af[0];
            int bi = 0;
            #pragma unroll
            for (int i = 1; i < K_; i++) {
                if (af[i] > bv) { bv = af[i]; bi = i; }
            }
            s_last[g] = bi;
        }
        GBAR();
        const int last = s_last[g];
        float* ob = out + (size_t)b * T;

        if (j >= 32) {
            // ---- warp 1: tail outputs (overlaps warp 0's backward) ----
            const float lastf = (float)last;
            for (int tau = (len - 1) + (j - 32); tau < T; tau += 32)
                ob[tau] = lastf;
        } else if (len >= 2) {
            // ---- warp 0: backward decode along the taken path ----
            const int lane = j;
            int tag = last;

            #pragma unroll
            for (int rr = 0; rr < 4; rr++) {
                int l = lane + rr * 32;
                int s = l >> 4;
                int c = (l & 15) * 4;
                int row = len - 1 - s; if (row < 0) row = 0;
                cp_async16(su_base + (uint32_t)(s * K_ + c) * 4,
                           arow + (size_t)row * K_ + c);
            }
            cp_commit();

            int bbuf = 0;
            for (int tb = len; tb >= 2; tb -= 8) {
                if (tb - 8 >= 2) {
                    #pragma unroll
                    for (int rr = 0; rr < 4; rr++) {
                        int l = lane + rr * 32;
                        int s = l >> 4;
                        int c = (l & 15) * 4;
                        int row = tb - 9 - s; if (row < 0) row = 0;
                        cp_async16(su_base + (uint32_t)(((bbuf ^ 1) * 8 + s) * K_ + c) * 4,
                                   arow + (size_t)row * K_ + c);
                    }
                }
                cp_commit();
                cp_wait<1>();
                __syncwarp();

                const int tlo = (tb - 7 > 2) ? tb - 7 : 2;
                #pragma unroll
                for (int s = 0; s < 8; s++) {
                    const int t = tb - s;
                    if (t >= tlo) {
                        float2 a = ((const float2*)&s_u[g][bbuf][s][0])[lane];
                        float2 tt = ((const float2*)(s_transT + tag * K_))[lane];
                        float c0 = a.x + tt.x;
                        float c1 = a.y + tt.y;
                        float v; int li;
                        if (c0 >= c1) { v = c0; li = 2 * lane; }
                        else          { v = c1; li = 2 * lane + 1; }
                        unsigned bits = __float_as_uint(v);
                        unsigned key = ((int)bits < 0) ? ~bits
                                                       : (bits | 0x80000000u);
                        unsigned mx = __reduce_max_sync(0xffffffffu, key);
                        unsigned sel = (key == mx) ? (unsigned)(K_ - 1 - li) : 0u;
                        unsigned w = __reduce_max_sync(0xffffffffu, sel);
                        tag = (K_ - 1) - (int)w;
                        if (lane == 0) ob[t - 2] = (float)tag;
                    }
                }
                bbuf ^= 1;
            }
        }
        // Protect s_u[g] reuse across sequences.
        GBAR();
    }
    #undef GBAR
}

extern "C" void kernel_launch(void* const* d_in, const int* in_sizes, int n_in,
                              void* d_out, int out_size) {
    // ----- identify inputs by SIZE, not position -----
    int iu = 0;
    for (int i = 1; i < n_in; i++)
        if (in_sizes[i] > in_sizes[iu]) iu = i;

    int pair[2] = {-1, -1};
    int ilen = -1;
    for (int i = 0; i < n_in; i++) {
        if (i == iu) continue;
        for (int k = 0; k < n_in; k++) {
            if (k == i || k == iu) continue;
            if (in_sizes[k] == in_sizes[i]) { pair[0] = i < k ? i : k; pair[1] = i < k ? k : i; }
        }
    }
    for (int i = 0; i < n_in; i++)
        if (i != iu && i != pair[0] && i != pair[1]) ilen = i;
    if (ilen < 0) { iu = 0; ilen = 1; pair[0] = 2; pair[1] = 3; }

    const float* unary   = (const float*)d_in[iu];
    const int*   lengths = (const int*)d_in[ilen];
    const float* c0      = (const float*)d_in[pair[0]];
    const float* c1      = (const float*)d_in[pair[1]];
    float* out = (float*)d_out;

    const int B = in_sizes[ilen];
    const int T = (int)((long long)in_sizes[iu] / ((long long)B * K_));

    prelude_kernel<<<65, 1024>>>(c0, c1, lengths, T, B);
    viterbi_kernel<<<NWORK_BLOCKS, 128>>>(unary, lengths, out, T, B);
}